// round 7
// baseline (speedup 1.0000x reference)
#include <cuda_runtime.h>
#include <cuda_bf16.h>
#include <cstdint>

typedef unsigned long long u64;
typedef unsigned int u32;
typedef unsigned short u16;

#define IN_F    66
#define EN      50
#define AN      20
#define MROW    128
#define THREADS 384
#define CHCOLS  120                   // score cols per chunk = 6 features
#define CHUNKS  11
#define CHUNKB  30720                 // 2(hl) x 15(ntile) x 4(kstep) x 32 lanes x 8B

// smem layout (bytes)
#define OFF_W0   0
#define OFF_W1   30720
#define OFF_E    61440                // Ehi tile 16KB (aliased as E_W f32 stage in phase A)
#define OFF_ELO  77824                // Elo tile 16KB
#define OFF_PC   94208                // float[2][128][8] p staging = 8192 (double-buffered)
#define OFF_MB   102400               // 2 mbarriers
#define SMEM_SZ  102416

__device__ __align__(1024) unsigned char g_W2s[CHUNKS * CHUNKB];

// ---------------- helpers ----------------
__device__ __forceinline__ u32 smem_u32(const void* p) {
    u32 a; asm("{ .reg .u64 t; cvta.to.shared.u64 t, %1; cvt.u32.u64 %0, t; }" : "=r"(a) : "l"(p));
    return a;
}
__device__ __forceinline__ u64 pack2(float lo, float hi) {
    u64 r; asm("mov.b64 %0, {%1, %2};" : "=l"(r) : "f"(lo), "f"(hi)); return r;
}
__device__ __forceinline__ float2 unpack2(u64 v) {
    float a, b; asm("mov.b64 {%0, %1}, %2;" : "=f"(a), "=f"(b) : "l"(v)); return make_float2(a, b);
}
__device__ __forceinline__ u64 ffma2(u64 a, u64 b, u64 c) {
    u64 d; asm("fma.rn.f32x2 %0, %1, %2, %3;" : "=l"(d) : "l"(a), "l"(b), "l"(c)); return d;
}
__device__ __forceinline__ float fast_tanh(float x) {
    x = fminf(fmaxf(x, -15.0f), 15.0f);
    float t = __expf(2.0f * x);
    return __fdividef(t - 1.0f, t + 1.0f);
}
__device__ __forceinline__ void ldsm_x4(u32& r0, u32& r1, u32& r2, u32& r3, u32 a) {
    asm volatile("ldmatrix.sync.aligned.m8n8.x4.shared.b16 {%0,%1,%2,%3}, [%4];"
        : "=r"(r0), "=r"(r1), "=r"(r2), "=r"(r3) : "r"(a));
}
__device__ __forceinline__ void lds_v2(u32& r0, u32& r1, u32 a) {
    asm volatile("ld.shared.v2.u32 {%0,%1}, [%2];" : "=r"(r0), "=r"(r1) : "r"(a));
}
__device__ __forceinline__ void mma_bf16(float* d, const u32* a, u32 b0, u32 b1) {
    asm volatile("mma.sync.aligned.m16n8k16.row.col.f32.bf16.bf16.f32 "
        "{%0,%1,%2,%3}, {%4,%5,%6,%7}, {%8,%9}, {%0,%1,%2,%3};"
        : "+f"(d[0]), "+f"(d[1]), "+f"(d[2]), "+f"(d[3])
        : "r"(a[0]), "r"(a[1]), "r"(a[2]), "r"(a[3]), "r"(b0), "r"(b1));
}
#define MBAR_INIT(a, c) asm volatile("mbarrier.init.shared.b64 [%0], %1;" :: "r"(a), "r"((u32)(c)) : "memory")
#define MBAR_EXPECT(a, b) asm volatile("mbarrier.arrive.expect_tx.shared.b64 _, [%0], %1;" :: "r"(a), "r"((u32)(b)) : "memory")
#define MBAR_WAIT(a, par) do { \
    u32 _m = (a), _p = (par), _d; \
    asm volatile("{\n\t.reg .pred p;\n\tmbarrier.try_wait.parity.acquire.cta.shared::cta.b64 p, [%1], %2;\n\tselp.b32 %0,1,0,p;\n\t}" \
        : "=r"(_d) : "r"(_m), "r"(_p) : "memory"); \
    if (!_d) { \
        asm volatile("{\n\t.reg .pred P;\n\tWL%=:\n\tmbarrier.try_wait.parity.acquire.cta.shared::cta.b64 P, [%0], %1, 0x989680;\n\t@P bra.uni WD%=;\n\tbra.uni WL%=;\n\tWD%=:\n\t}" \
            :: "r"(_m), "r"(_p) : "memory"); \
    } } while (0)
#define BULK_CP(dst, src, bytes, mb) \
    asm volatile("cp.async.bulk.shared::cta.global.mbarrier::complete_tx::bytes [%0], [%1], %2, [%3];" \
        :: "r"(dst), "l"(src), "r"((u32)(bytes)), "r"(mb) : "memory")

__device__ __forceinline__ u16 bf_bits(__nv_bfloat16 h) { return *(u16*)&h; }

// ---------------- prep: pack W2(+bias) into HMMA B-fragment order, bf16 hi/lo ----------------
__global__ void prep_kernel(const float* __restrict__ A_W, const float* __restrict__ A_b) {
    int c = blockIdx.x;
    u64* dst = (u64*)(g_W2s + (size_t)c * CHUNKB);
    for (int idx = threadIdx.x; idx < 2 * 15 * 4 * 32; idx += blockDim.x) {
        int lane = idx & 31;
        int ks   = (idx >> 5) & 3;
        int nt   = (idx >> 7) % 15;
        int hl   = idx / 1920;
        int gid = lane >> 2, tig = lane & 3;
        int j = c * CHCOLS + nt * 8 + gid;      // global score column
        int i = j / AN, a = j % AN;
        int k0 = ks * 16 + 2 * tig;
        u16 bits[4];
        #pragma unroll
        for (int t = 0; t < 4; t++) {
            int k = k0 + (t & 1) + (t >> 1) * 8;   // k0, k0+1, k0+8, k0+9
            float w = 0.0f;
            if (k < EN)       w = A_W[(i * EN + k) * AN + a];
            else if (k == EN) w = A_b[i * AN + a];
            __nv_bfloat16 hi = __float2bfloat16(w);
            if (hl == 0) bits[t] = bf_bits(hi);
            else         bits[t] = bf_bits(__float2bfloat16(w - __bfloat162float(hi)));
        }
        u32 b0 = (u32)bits[0] | ((u32)bits[1] << 16);
        u32 b1 = (u32)bits[2] | ((u32)bits[3] << 16);
        dst[((hl * 15 + nt) * 4 + ks) * 32 + lane] = (u64)b0 | ((u64)b1 << 32);
    }
}

// ---------------- main kernel: 12 warps = (m-quarter x n-subchunk) ----------------
__global__ void __launch_bounds__(THREADS)
attn_hmma_kernel(const float* __restrict__ x,
                 const float* __restrict__ E_W,
                 const float* __restrict__ E_b,
                 float* __restrict__ out,
                 int Btotal)
{
    extern __shared__ unsigned char smem[];
    u32 sb = smem_u32(smem);
    const int tid = threadIdx.x;
    const int wid = tid >> 5;
    const int lane = tid & 31;
    const int gid = lane >> 2, tig = lane & 3;
    const int mq = wid & 3;          // m-quarter: rows [mq*32, mq*32+32)
    const int nb = wid >> 2;         // n-subchunk: cols [nb*40, nb*40+40) = 2 groups
    const int rowBase = blockIdx.x * MROW;

    // mbarriers init, then kick both weight prefetches (one per issuing thread)
    if (tid == 0) {
        MBAR_INIT(sb + OFF_MB, 1);
        MBAR_INIT(sb + OFF_MB + 8, 1);
        asm volatile("fence.proxy.async.shared::cta;" ::: "memory");
    }
    __syncthreads();
    if (tid == 0) {
        MBAR_EXPECT(sb + OFF_MB, CHUNKB);
        BULK_CP(sb + OFF_W0, (const void*)g_W2s, CHUNKB, sb + OFF_MB);
    } else if (tid == 32) {
        MBAR_EXPECT(sb + OFF_MB + 8, CHUNKB);
        BULK_CP(sb + OFF_W1, (const void*)(g_W2s + CHUNKB), CHUNKB, sb + OFF_MB + 8);
    }

    // stage E_W (f32) into the E-tile region (temporary alias)
    float* s_EW = (float*)(smem + OFF_E);
    for (int idx = tid; idx < IN_F * EN; idx += THREADS) s_EW[idx] = E_W[idx];
    __syncthreads();

    // ---- phase A: 3 threads per row, disjoint E-column slices ----
    {
        int row = tid & 127;
        int j   = tid >> 7;                       // 0,1,2 (uniform per warp)
        int c0  = (j == 0) ? 0 : (j == 1 ? 16 : 32);
        int n2  = (j == 2) ? 9 : 8;               // u64 accumulators (cols c0..c0+2*n2)
        u64 acc2[9];
        const u64* ebp = (const u64*)E_b;
        #pragma unroll
        for (int e2 = 0; e2 < 9; e2++) if (e2 < n2) acc2[e2] = ebp[c0 / 2 + e2];
        const float* xrow = x + (size_t)(rowBase + row) * IN_F;
        const u64* ew64 = (const u64*)s_EW;
        for (int k = 0; k < IN_F; k++) {
            float xk = xrow[k];
            u64 x2 = pack2(xk, xk);
            const u64* wr = ew64 + k * (EN / 2) + c0 / 2;
            #pragma unroll
            for (int e2 = 0; e2 < 9; e2++) if (e2 < n2) acc2[e2] = ffma2(x2, wr[e2], acc2[e2]);
        }
        float Ec[18];
        #pragma unroll
        for (int e2 = 0; e2 < 9; e2++) {
            if (e2 < n2) {
                float2 v = unpack2(acc2[e2]);
                Ec[2 * e2]     = fast_tanh(v.x);
                Ec[2 * e2 + 1] = fast_tanh(v.y);
            }
        }
        __syncthreads();   // all E_W reads done before tile overwrite

        unsigned char* ahi = smem + OFF_E;
        unsigned char* alo = smem + OFF_ELO;
        #pragma unroll
        for (int e = 0; e < 18; e++) {
            if (e < 2 * n2) {
                float v = Ec[e];
                __nv_bfloat16 hi = __float2bfloat16(v);
                __nv_bfloat16 lo = __float2bfloat16(v - __bfloat162float(hi));
                u32 off = row * 128 + (c0 + e) * 2;
                u32 sw = off ^ ((off >> 3) & 0x70);
                *(u16*)(ahi + sw) = bf_bits(hi);
                *(u16*)(alo + sw) = bf_bits(lo);
            }
        }
        if (j == 2) {
            #pragma unroll
            for (int k = EN; k < 64; k++) {
                u32 off = row * 128 + k * 2;
                u32 sw = off ^ ((off >> 3) & 0x70);
                *(u16*)(ahi + sw) = (k == EN) ? (u16)0x3F80 : (u16)0;   // bias col = 1.0
                *(u16*)(alo + sw) = 0;
            }
        }
    }
    __syncthreads();

    // ---- hoist A fragments (this warp's 32 rows) into registers ----
    u32 Ahi[2][4][4], Alo[2][4][4];
    {
        int rowl = mq * 32 + (lane & 15);
        int kofl = (lane >> 4) * 16;
        #pragma unroll
        for (int mt = 0; mt < 2; mt++) {
            #pragma unroll
            for (int ks = 0; ks < 4; ks++) {
                u32 off = (rowl + 16 * mt) * 128 + ks * 32 + kofl;
                u32 sw = off ^ ((off >> 3) & 0x70);
                ldsm_x4(Ahi[mt][ks][0], Ahi[mt][ks][1], Ahi[mt][ks][2], Ahi[mt][ks][3], sb + OFF_E + sw);
                ldsm_x4(Alo[mt][ks][0], Alo[mt][ks][1], Alo[mt][ks][2], Alo[mt][ks][3], sb + OFF_ELO + sw);
            }
        }
    }

    float* s_pc = (float*)(smem + OFF_PC);   // [2][128][8]

    // ---- chunk loop ----
    for (int c = 0; c < CHUNKS; c++) {
        u32 wb = sb + ((c & 1) ? OFF_W1 : OFF_W0);
        MBAR_WAIT(sb + OFF_MB + 8 * (c & 1), (c >> 1) & 1);

        float acc[2][5][4];
        #pragma unroll
        for (int mt = 0; mt < 2; mt++)
            #pragma unroll
            for (int nt = 0; nt < 5; nt++)
                #pragma unroll
                for (int e = 0; e < 4; e++) acc[mt][nt][e] = 0.0f;

        #pragma unroll
        for (int ks = 0; ks < 4; ks++) {
            #pragma unroll
            for (int nt = 0; nt < 5; nt++) {
                int ntg = nb * 5 + nt;
                u32 bh0, bh1, bl0, bl1;
                lds_v2(bh0, bh1, wb + (u32)((ntg * 4 + ks) * 256 + lane * 8));
                lds_v2(bl0, bl1, wb + (u32)(((15 + ntg) * 4 + ks) * 256 + lane * 8));
                #pragma unroll
                for (int mt = 0; mt < 2; mt++) {
                    mma_bf16(acc[mt][nt], Ahi[mt][ks], bh0, bh1);
                    mma_bf16(acc[mt][nt], Ahi[mt][ks], bl0, bl1);
                    mma_bf16(acc[mt][nt], Alo[mt][ks], bh0, bh1);
                }
            }
        }

        // exp (no max-subtract; logits are small) then quad softmax
        #pragma unroll
        for (int mt = 0; mt < 2; mt++)
            #pragma unroll
            for (int nt = 0; nt < 5; nt++)
                #pragma unroll
                for (int e = 0; e < 4; e++) acc[mt][nt][e] = __expf(acc[mt][nt][e]);

        float* pc = s_pc + (c & 1) * 128 * 8;
        #pragma unroll
        for (int mt = 0; mt < 2; mt++) {
            #pragma unroll
            for (int half = 0; half < 2; half++) {
                float s0 = 0.0f, s1 = 0.0f;
                #pragma unroll
                for (int nt = 0; nt < 5; nt++) {
                    #pragma unroll
                    for (int j = 0; j < 2; j++) {
                        float v = acc[mt][nt][half * 2 + j];
                        if (nt < 2) s0 += v;
                        else if (nt > 2) s1 += v;
                        else { if (2 * tig + j < 4) s0 += v; else s1 += v; }
                    }
                }
                s0 += __shfl_xor_sync(0xffffffffu, s0, 1);
                s0 += __shfl_xor_sync(0xffffffffu, s0, 2);
                s1 += __shfl_xor_sync(0xffffffffu, s1, 1);
                s1 += __shfl_xor_sync(0xffffffffu, s1, 2);
                int row = mq * 32 + 16 * mt + gid + 8 * half;
                if (tig == 0)
                    pc[row * 8 + nb * 2 + 0] = __fdividef(acc[mt][0][half * 2 + 1], s0);
                if (tig == 2)
                    pc[row * 8 + nb * 2 + 1] = __fdividef(acc[mt][2][half * 2 + 1], s1);
            }
        }

        __syncthreads();   // pc complete; W buffer fully consumed by all warps
        if (tid == 0 && c + 2 < CHUNKS) {
            u32 mb = sb + OFF_MB + 8 * (c & 1);
            MBAR_EXPECT(mb, CHUNKB);
            BULK_CP(wb, (const void*)(g_W2s + (size_t)(c + 2) * CHUNKB), CHUNKB, mb);
        }

        // fused multiply for this chunk's 6 features (pc is double-buffered,
        // so no trailing barrier: next chunk's softmax writes the other buffer)
        #pragma unroll
        for (int idx = tid; idx < MROW * 6; idx += THREADS) {
            int row = idx / 6, k = idx - row * 6;
            size_t g = (size_t)(rowBase + row) * IN_F + c * 6 + k;
            out[g] = x[g] * pc[row * 8 + k];
        }
    }
}

extern "C" void kernel_launch(void* const* d_in, const int* in_sizes, int n_in,
                              void* d_out, int out_size)
{
    const float* x   = (const float*)d_in[0];
    const float* E_W = (const float*)d_in[1];
    const float* E_b = (const float*)d_in[2];
    const float* A_W = (const float*)d_in[3];
    const float* A_b = (const float*)d_in[4];
    float* out = (float*)d_out;

    const int Btotal = in_sizes[0] / IN_F;

    prep_kernel<<<CHUNKS, 256>>>(A_W, A_b);

    cudaFuncSetAttribute(attn_hmma_kernel,
                         cudaFuncAttributeMaxDynamicSharedMemorySize, SMEM_SZ);
    const int grid = (Btotal + MROW - 1) / MROW;
    attn_hmma_kernel<<<grid, THREADS, SMEM_SZ>>>(x, E_W, E_b, out, Btotal);
}

// round 9
// speedup vs baseline: 1.0742x; 1.0742x over previous
#include <cuda_runtime.h>
#include <cuda_bf16.h>
#include <cstdint>

typedef unsigned long long u64;
typedef unsigned int u32;
typedef unsigned short u16;

#define IN_F    66
#define EN      50
#define AN      20
#define MROW    256
#define THREADS 128
#define CHCOLS  120                   // score cols per chunk = 6 features
#define CHUNKS  11
#define CHUNKB  30720                 // 15(ntile) x 4(kstep) x 32 lanes x 16B {hi,hi,lo,lo}

// smem layout (bytes)
// R0 [0, 65536): phase A = {w,w} E-weights (26400) then Ehi(32768)+Elo(32768);
//                chunk phase = W0(30720) @0 + W1(30720) @30720
#define OFF_W0   0
#define OFF_W1   30720
#define OFF_EHI  0
#define OFF_ELO  32768
#define OFF_PC   65536                // float[2][256][8] = 16384 (double-buffered p)
#define OFF_MB   81920                // 2 mbarriers
#define SMEM_SZ  81936

__device__ __align__(1024) unsigned char g_W2s[CHUNKS * CHUNKB];

// ---------------- helpers ----------------
__device__ __forceinline__ u32 smem_u32(const void* p) {
    u32 a; asm("{ .reg .u64 t; cvta.to.shared.u64 t, %1; cvt.u32.u64 %0, t; }" : "=r"(a) : "l"(p));
    return a;
}
__device__ __forceinline__ u64 pack2(float lo, float hi) {
    u64 r; asm("mov.b64 %0, {%1, %2};" : "=l"(r) : "f"(lo), "f"(hi)); return r;
}
__device__ __forceinline__ float2 unpack2(u64 v) {
    float a, b; asm("mov.b64 {%0, %1}, %2;" : "=f"(a), "=f"(b) : "l"(v)); return make_float2(a, b);
}
__device__ __forceinline__ u64 ffma2(u64 a, u64 b, u64 c) {
    u64 d; asm("fma.rn.f32x2 %0, %1, %2, %3;" : "=l"(d) : "l"(a), "l"(b), "l"(c)); return d;
}
__device__ __forceinline__ float fast_tanh(float x) {
    x = fminf(fmaxf(x, -15.0f), 15.0f);
    float t = __expf(2.0f * x);
    return __fdividef(t - 1.0f, t + 1.0f);
}
__device__ __forceinline__ void ldsm_x4(u32& r0, u32& r1, u32& r2, u32& r3, u32 a) {
    asm volatile("ldmatrix.sync.aligned.m8n8.x4.shared.b16 {%0,%1,%2,%3}, [%4];"
        : "=r"(r0), "=r"(r1), "=r"(r2), "=r"(r3) : "r"(a));
}
__device__ __forceinline__ void lds_v4(u32& r0, u32& r1, u32& r2, u32& r3, u32 a) {
    asm volatile("ld.shared.v4.u32 {%0,%1,%2,%3}, [%4];"
        : "=r"(r0), "=r"(r1), "=r"(r2), "=r"(r3) : "r"(a));
}
__device__ __forceinline__ void mma_bf16(float* d, const u32* a, u32 b0, u32 b1) {
    asm volatile("mma.sync.aligned.m16n8k16.row.col.f32.bf16.bf16.f32 "
        "{%0,%1,%2,%3}, {%4,%5,%6,%7}, {%8,%9}, {%0,%1,%2,%3};"
        : "+f"(d[0]), "+f"(d[1]), "+f"(d[2]), "+f"(d[3])
        : "r"(a[0]), "r"(a[1]), "r"(a[2]), "r"(a[3]), "r"(b0), "r"(b1));
}
#define MBAR_INIT(a, c) asm volatile("mbarrier.init.shared.b64 [%0], %1;" :: "r"(a), "r"((u32)(c)) : "memory")
#define MBAR_EXPECT(a, b) asm volatile("mbarrier.arrive.expect_tx.shared.b64 _, [%0], %1;" :: "r"(a), "r"((u32)(b)) : "memory")
#define MBAR_WAIT(a, par) do { \
    u32 _m = (a), _p = (par), _d; \
    asm volatile("{\n\t.reg .pred p;\n\tmbarrier.try_wait.parity.acquire.cta.shared::cta.b64 p, [%1], %2;\n\tselp.b32 %0,1,0,p;\n\t}" \
        : "=r"(_d) : "r"(_m), "r"(_p) : "memory"); \
    if (!_d) { \
        asm volatile("{\n\t.reg .pred P;\n\tWL%=:\n\tmbarrier.try_wait.parity.acquire.cta.shared::cta.b64 P, [%0], %1, 0x989680;\n\t@P bra.uni WD%=;\n\tbra.uni WL%=;\n\tWD%=:\n\t}" \
            :: "r"(_m), "r"(_p) : "memory"); \
    } } while (0)
#define BULK_CP(dst, src, bytes, mb) \
    asm volatile("cp.async.bulk.shared::cta.global.mbarrier::complete_tx::bytes [%0], [%1], %2, [%3];" \
        :: "r"(dst), "l"(src), "r"((u32)(bytes)), "r"(mb) : "memory")

__device__ __forceinline__ u16 bf_bits(__nv_bfloat16 h) { return *(u16*)&h; }

// ---------------- prep: pack W2(+bias) into HMMA B-fragment order, hi/lo interleaved 16B ----------------
__global__ void prep_kernel(const float* __restrict__ A_W, const float* __restrict__ A_b) {
    int c = blockIdx.x;
    u32* dst = (u32*)(g_W2s + (size_t)c * CHUNKB);
    for (int idx = threadIdx.x; idx < 15 * 4 * 32; idx += blockDim.x) {
        int lane = idx & 31;
        int ks   = (idx >> 5) & 3;
        int nt   = idx >> 7;                    // 0..14
        int gid = lane >> 2, tig = lane & 3;
        int j = c * CHCOLS + nt * 8 + gid;      // global score column
        int i = j / AN, a = j % AN;
        int k0 = ks * 16 + 2 * tig;
        u16 hb[4], lb[4];
        #pragma unroll
        for (int t = 0; t < 4; t++) {
            int k = k0 + (t & 1) + (t >> 1) * 8;   // k0, k0+1, k0+8, k0+9
            float w = 0.0f;
            if (k < EN)       w = A_W[(i * EN + k) * AN + a];
            else if (k == EN) w = A_b[i * AN + a];
            __nv_bfloat16 hi = __float2bfloat16(w);
            hb[t] = bf_bits(hi);
            lb[t] = bf_bits(__float2bfloat16(w - __bfloat162float(hi)));
        }
        u32* d4 = dst + ((nt * 4 + ks) * 32 + lane) * 4;
        d4[0] = (u32)hb[0] | ((u32)hb[1] << 16);
        d4[1] = (u32)hb[2] | ((u32)hb[3] << 16);
        d4[2] = (u32)lb[0] | ((u32)lb[1] << 16);
        d4[3] = (u32)lb[2] | ((u32)lb[3] << 16);
    }
}

// ---------------- main kernel: 4 warps, 256 rows (4 mt each), 2 CTAs/SM ----------------
__global__ void __launch_bounds__(THREADS, 2)
attn_hmma_kernel(const float* __restrict__ x,
                 const float* __restrict__ E_W,
                 const float* __restrict__ E_b,
                 float* __restrict__ out,
                 int Btotal)
{
    extern __shared__ unsigned char smem[];
    u32 sb = smem_u32(smem);
    const int tid = threadIdx.x;
    const int wid = tid >> 5;
    const int lane = tid & 31;
    const int gid = lane >> 2, tig = lane & 3;
    const int rowBase = blockIdx.x * MROW;

    if (tid == 0) {
        MBAR_INIT(sb + OFF_MB, 1);
        MBAR_INIT(sb + OFF_MB + 8, 1);
        asm volatile("fence.proxy.async.shared::cta;" ::: "memory");
    }

    // stage {w,w}-replicated E weights into R0 (phase-A alias)
    u64* s_EW2 = (u64*)smem;
    for (int idx = tid; idx < IN_F * EN; idx += THREADS) {
        float w = E_W[idx];
        s_EW2[idx] = pack2(w, w);
    }
    __syncthreads();

    // ---- phase A: each thread owns rows (tid, tid+128), packed in f32x2 ----
    {
        u64 E2[EN];
        const float* ebf = E_b;
        #pragma unroll
        for (int e = 0; e < EN; e++) { float b = ebf[e]; E2[e] = pack2(b, b); }
        const float* xr0 = x + (size_t)(rowBase + tid) * IN_F;
        const float* xr1 = x + (size_t)(rowBase + tid + 128) * IN_F;
        for (int k = 0; k < IN_F; k++) {
            u64 x2 = pack2(xr0[k], xr1[k]);
            const ulonglong2* wr = (const ulonglong2*)(s_EW2 + k * EN);
            #pragma unroll
            for (int e2 = 0; e2 < EN / 2; e2++) {
                ulonglong2 w = wr[e2];
                E2[2 * e2]     = ffma2(x2, w.x, E2[2 * e2]);
                E2[2 * e2 + 1] = ffma2(x2, w.y, E2[2 * e2 + 1]);
            }
        }
        __syncthreads();   // s_EW2 dead; R0 becomes E tiles

        unsigned char* ahi = smem + OFF_EHI;
        unsigned char* alo = smem + OFF_ELO;
        #pragma unroll
        for (int e = 0; e < EN; e++) {
            float2 v = unpack2(E2[e]);
            float t0 = fast_tanh(v.x), t1 = fast_tanh(v.y);
            __nv_bfloat16 h0 = __float2bfloat16(t0);
            __nv_bfloat16 h1 = __float2bfloat16(t1);
            u32 o0 = tid * 128 + e * 2;
            u32 o1 = (tid + 128) * 128 + e * 2;
            u32 s0 = o0 ^ ((o0 >> 3) & 0x70);
            u32 s1 = o1 ^ ((o1 >> 3) & 0x70);
            *(u16*)(ahi + s0) = bf_bits(h0);
            *(u16*)(ahi + s1) = bf_bits(h1);
            *(u16*)(alo + s0) = bf_bits(__float2bfloat16(t0 - __bfloat162float(h0)));
            *(u16*)(alo + s1) = bf_bits(__float2bfloat16(t1 - __bfloat162float(h1)));
        }
        #pragma unroll
        for (int k = EN; k < 64; k++) {
            u32 o0 = tid * 128 + k * 2;
            u32 o1 = (tid + 128) * 128 + k * 2;
            u32 s0 = o0 ^ ((o0 >> 3) & 0x70);
            u32 s1 = o1 ^ ((o1 >> 3) & 0x70);
            u16 v = (k == EN) ? (u16)0x3F80 : (u16)0;   // bias col = 1.0
            *(u16*)(smem + OFF_EHI + s0) = v;
            *(u16*)(smem + OFF_EHI + s1) = v;
            *(u16*)(smem + OFF_ELO + s0) = 0;
            *(u16*)(smem + OFF_ELO + s1) = 0;
        }
    }
    __syncthreads();

    // ---- hoist A fragments (this warp's 64 rows = 4 m-tiles) into registers ----
    u32 Ahi[4][4][4], Alo[4][4][4];
    {
        int rowl = wid * 64 + (lane & 15);
        int kofl = (lane >> 4) * 16;
        #pragma unroll
        for (int mt = 0; mt < 4; mt++) {
            #pragma unroll
            for (int ks = 0; ks < 4; ks++) {
                u32 off = (rowl + 16 * mt) * 128 + ks * 32 + kofl;
                u32 sw = off ^ ((off >> 3) & 0x70);
                ldsm_x4(Ahi[mt][ks][0], Ahi[mt][ks][1], Ahi[mt][ks][2], Ahi[mt][ks][3], sb + OFF_EHI + sw);
                ldsm_x4(Alo[mt][ks][0], Alo[mt][ks][1], Alo[mt][ks][2], Alo[mt][ks][3], sb + OFF_ELO + sw);
            }
        }
    }
    __syncthreads();   // E tiles dead; R0 becomes W double-buffer

    if (tid == 0) {
        MBAR_EXPECT(sb + OFF_MB, CHUNKB);
        BULK_CP(sb + OFF_W0, (const void*)g_W2s, CHUNKB, sb + OFF_MB);
        MBAR_EXPECT(sb + OFF_MB + 8, CHUNKB);
        BULK_CP(sb + OFF_W1, (const void*)(g_W2s + CHUNKB), CHUNKB, sb + OFF_MB + 8);
    }

    float* s_pc = (float*)(smem + OFF_PC);   // [2][256][8]

    // ---- chunk loop ----
    for (int c = 0; c < CHUNKS; c++) {
        u32 wb = sb + ((c & 1) ? OFF_W1 : OFF_W0);
        MBAR_WAIT(sb + OFF_MB + 8 * (c & 1), (c >> 1) & 1);
        float* pc = s_pc + (c & 1) * MROW * 8;

        #pragma unroll 1
        for (int nb = 0; nb < 3; nb++) {               // 3 subchunks of 40 cols (2 groups)
            float acc[4][5][4];
            #pragma unroll
            for (int mt = 0; mt < 4; mt++)
                #pragma unroll
                for (int nt = 0; nt < 5; nt++)
                    #pragma unroll
                    for (int e = 0; e < 4; e++) acc[mt][nt][e] = 0.0f;

            #pragma unroll
            for (int ks = 0; ks < 4; ks++) {
                #pragma unroll
                for (int nt = 0; nt < 5; nt++) {
                    int ntg = nb * 5 + nt;
                    u32 bh0, bh1, bl0, bl1;
                    lds_v4(bh0, bh1, bl0, bl1, wb + (u32)((ntg * 4 + ks) * 512 + lane * 16));
                    #pragma unroll
                    for (int mt = 0; mt < 4; mt++) {
                        mma_bf16(acc[mt][nt], Ahi[mt][ks], bh0, bh1);
                        mma_bf16(acc[mt][nt], Ahi[mt][ks], bl0, bl1);
                        mma_bf16(acc[mt][nt], Alo[mt][ks], bh0, bh1);
                    }
                }
            }

            // exp (no max-subtract; logits are small) then quad softmax
            #pragma unroll
            for (int mt = 0; mt < 4; mt++)
                #pragma unroll
                for (int nt = 0; nt < 5; nt++)
                    #pragma unroll
                    for (int e = 0; e < 4; e++) acc[mt][nt][e] = __expf(acc[mt][nt][e]);

            #pragma unroll
            for (int mt = 0; mt < 4; mt++) {
                #pragma unroll
                for (int half = 0; half < 2; half++) {
                    float s0 = 0.0f, s1 = 0.0f;
                    #pragma unroll
                    for (int nt = 0; nt < 5; nt++) {
                        #pragma unroll
                        for (int j = 0; j < 2; j++) {
                            float v = acc[mt][nt][half * 2 + j];
                            if (nt < 2) s0 += v;
                            else if (nt > 2) s1 += v;
                            else { if (2 * tig + j < 4) s0 += v; else s1 += v; }
                        }
                    }
                    s0 += __shfl_xor_sync(0xffffffffu, s0, 1);
                    s0 += __shfl_xor_sync(0xffffffffu, s0, 2);
                    s1 += __shfl_xor_sync(0xffffffffu, s1, 1);
                    s1 += __shfl_xor_sync(0xffffffffu, s1, 2);
                    int row = wid * 64 + 16 * mt + gid + 8 * half;
                    if (tig == 0)
                        pc[row * 8 + nb * 2 + 0] = __fdividef(acc[mt][0][half * 2 + 1], s0);
                    if (tig == 2)
                        pc[row * 8 + nb * 2 + 1] = __fdividef(acc[mt][2][half * 2 + 1], s1);
                }
            }
        }

        __syncthreads();   // pc complete; W buffer fully consumed by all warps
        if (tid == 0 && c + 2 < CHUNKS) {
            u32 mb = sb + OFF_MB + 8 * (c & 1);
            MBAR_EXPECT(mb, CHUNKB);
            BULK_CP(wb, (const void*)(g_W2s + (size_t)(c + 2) * CHUNKB), CHUNKB, mb);
        }

        // fused multiply for this chunk's 6 features (pc double-buffered: no trailing barrier)
        for (int r = tid; r < MROW; r += THREADS) {
            size_t g = (size_t)(rowBase + r) * IN_F + c * 6;
            #pragma unroll
            for (int k = 0; k < 6; k++) out[g + k] = x[g + k] * pc[r * 8 + k];
        }
    }
}

extern "C" void kernel_launch(void* const* d_in, const int* in_sizes, int n_in,
                              void* d_out, int out_size)
{
    const float* x   = (const float*)d_in[0];
    const float* E_W = (const float*)d_in[1];
    const float* E_b = (const float*)d_in[2];
    const float* A_W = (const float*)d_in[3];
    const float* A_b = (const float*)d_in[4];
    float* out = (float*)d_out;

    const int Btotal = in_sizes[0] / IN_F;

    prep_kernel<<<CHUNKS, 256>>>(A_W, A_b);

    cudaFuncSetAttribute(attn_hmma_kernel,
                         cudaFuncAttributeMaxDynamicSharedMemorySize, SMEM_SZ);
    const int grid = (Btotal + MROW - 1) / MROW;
    attn_hmma_kernel<<<grid, THREADS, SMEM_SZ>>>(x, E_W, E_b, out, Btotal);
}